// round 13
// baseline (speedup 1.0000x reference)
#include <cuda_runtime.h>
#include <cuda_fp16.h>
#include <cstdint>

#define DI __device__ __forceinline__
typedef unsigned long long ull;

constexpr int NT   = 256;  // 8 warps; warp w owns m-tile rows [16w, 16w+16)
constexpr int TILE = 128;  // items per CTA-tile

// ---------------- smem layout (bytes) ----------------
// Weight fragments: per layer, [ntile][ktile][lane] -> uint4 {bh.x,bh.y,bl.x,bl.y}
constexpr int O_WF1  = 0;        // 8*2*32*16 = 8192
constexpr int O_WF2  = 8192;     // 8*4*32*16 = 16384
constexpr int O_WF3  = 24576;    // 16384
constexpr int O_WF4  = 40960;    // 16384
constexpr int O_WF5  = 57344;    // 2*4*32*16 = 4096  (ends 61440)
constexpr int O_BIAS = 61440;    // 272 floats = 1088 (ends 62528)
constexpr int O_CTR  = 62528;    // 16 B (next-tile broadcast slot)
constexpr int O_FEAT = 62544;    // 128 rows * 40 halves * 2B = 10240
constexpr int O_OUTS = 72784;    // 128 rows * 9 floats * 4B = 4608 (DISJOINT from fB)
constexpr int SMEM_BYTES = 77392;   // x3 CTAs = 232,176 B < 233,472 B/SM

// ---------------- persistent work counter ----------------
__device__ int g_tile_ctr;
__global__ void reset_ctr_kernel(int v){ g_tile_ctr = v; }

// ---------------- packed f32x2 helpers ----------------
DI ull pack2(float x, float y){
    ull v;
    asm("mov.b64 %0, {%1,%2};" : "=l"(v)
        : "r"(__float_as_uint(x)), "r"(__float_as_uint(y)));
    return v;
}
DI float2 unpack2(ull v){
    unsigned lo, hi;
    asm("mov.b64 {%0,%1}, %2;" : "=r"(lo), "=r"(hi) : "l"(v));
    return make_float2(__uint_as_float(lo), __uint_as_float(hi));
}
DI ull mul2(ull a, ull b){ ull d; asm("mul.rn.f32x2 %0,%1,%2;" : "=l"(d) : "l"(a), "l"(b)); return d; }
DI ull add2(ull a, ull b){ ull d; asm("add.rn.f32x2 %0,%1,%2;" : "=l"(d) : "l"(a), "l"(b)); return d; }
DI ull fma2(ull a, ull b, ull c){ ull d; asm("fma.rn.f32x2 %0,%1,%2,%3;" : "=l"(d) : "l"(a), "l"(b), "l"(c)); return d; }
DI float rcp_a(float x){ float r; asm("rcp.approx.f32 %0,%1;" : "=f"(r) : "f"(x)); return r; }
DI float ex2_a(float x){ float r; asm("ex2.approx.f32 %0,%1;" : "=f"(r) : "f"(x)); return r; }
DI float sqrt_a(float x){ float r; asm("sqrt.approx.f32 %0,%1;" : "=f"(r) : "f"(x)); return r; }
DI ull dup2(float c){ unsigned u = __float_as_uint(c); return ((ull)u << 32) | u; }

// packed exact-GELU, restructured, 3-term A&S 7.1.25 erf (|err| <= 2.5e-5):
//   gelu(x) = 0.5(x+|x|) - 0.5|x|*pl(t)*e^{-x^2/2},  t = 1/(1 + p*|x|/sqrt2)
DI ull gelu2(ull x){
    const ull C_PC  = dup2(0.33272437f);      // 0.47047 / sqrt(2)
    const ull C_ONE = dup2(1.0f);
    const ull C_A3  = dup2(0.7478556f);
    const ull C_A2  = dup2(-0.0958798f);
    const ull C_A1  = dup2(0.3480242f);
    const ull C_ME  = dup2(-0.72134752044f);  // -log2(e)/2
    const ull C_H   = dup2(0.5f);
    const ull C_NH  = dup2(-0.5f);

    ull ax = x & 0x7FFFFFFF7FFFFFFFull;
    ull w  = fma2(ax, C_PC, C_ONE);
    float2 wf = unpack2(w);
    ull t  = pack2(rcp_a(wf.x), rcp_a(wf.y));
    ull pl = fma2(t, C_A3, C_A2);
    pl = fma2(t, pl, C_A1);
    pl = mul2(pl, t);
    ull x2 = mul2(x, x);
    ull mm = mul2(x2, C_ME);
    float2 mf = unpack2(mm);
    ull e  = pack2(ex2_a(mf.x), ex2_a(mf.y));
    ull pe = mul2(pl, e);
    pe = mul2(pe, ax);
    ull u = mul2(add2(x, ax), C_H);
    return fma2(pe, C_NH, u);
}

// packed f32 pair -> f16x2
DI unsigned cvt_h2(ull g){
    float2 gf = unpack2(g);
    unsigned h2;
    asm("cvt.rn.f16x2.f32 %0, %1, %2;" : "=r"(h2) : "f"(gf.y), "f"(gf.x));
    return h2;
}

DI void split2s(float v0, float v1, unsigned &hi, unsigned &lo){
    half h0 = __float2half_rn(v0), h1 = __float2half_rn(v1);
    half l0 = __float2half_rn(v0 - __half2float(h0));
    half l1 = __float2half_rn(v1 - __half2float(h1));
    hi = ((unsigned)__half_as_ushort(h1) << 16) | (unsigned)__half_as_ushort(h0);
    lo = ((unsigned)__half_as_ushort(l1) << 16) | (unsigned)__half_as_ushort(l0);
}

DI void mma16816(float (&c)[4], const unsigned (&a)[4], unsigned b0, unsigned b1){
    asm volatile(
        "mma.sync.aligned.m16n8k16.row.col.f32.f16.f16.f32 "
        "{%0,%1,%2,%3}, {%4,%5,%6,%7}, {%8,%9}, {%0,%1,%2,%3};"
        : "+f"(c[0]), "+f"(c[1]), "+f"(c[2]), "+f"(c[3])
        : "r"(a[0]), "r"(a[1]), "r"(a[2]), "r"(a[3]), "r"(b0), "r"(b1));
}

template<int NTI>
DI void init_acc1(float (&acc)[8][4], const float* bias, int lane){
    int t2 = (lane & 3) * 2;
    #pragma unroll
    for (int j = 0; j < NTI; j++){
        float2 b2v = *reinterpret_cast<const float2*>(bias + j*8 + t2);
        acc[j][0] = b2v.x; acc[j][1] = b2v.y;
        acc[j][2] = b2v.x; acc[j][3] = b2v.y;
    }
}

// one layer (single m-tile): Ah*Bh + Ah*Bl  (weights hi/lo packed in one uint4)
template<int KT, int NTI>
DI void mma_block1(float (&acc)[8][4],
                   const unsigned (&Ah)[4][4],
                   const uint4* __restrict__ wf, int lane){
    #pragma unroll
    for (int kt = 0; kt < KT; kt++){
        #pragma unroll
        for (int j = 0; j < NTI; j++){
            uint4 w = wf[(j*KT + kt)*32 + lane];
            mma16816(acc[j], Ah[kt], w.x, w.y);
            mma16816(acc[j], Ah[kt], w.z, w.w);
        }
    }
}

// D -> packed GELU -> next-layer A fragments (registers only)
DI void act_frags1(const float (&acc)[8][4], unsigned (&Ah)[4][4]){
    #pragma unroll
    for (int kk = 0; kk < 4; kk++)
    #pragma unroll
    for (int part = 0; part < 2; part++)
    #pragma unroll
    for (int pair = 0; pair < 2; pair++){
        int j = 2*kk + part;
        ull g = gelu2(pack2(acc[j][2*pair], acc[j][2*pair + 1]));
        Ah[kk][part*2 + pair] = cvt_h2(g);
    }
}

// A fragments for one 16-row m-tile from feature smem (row stride 40 halves)
template<int KT>
DI void load_feat_frags1(const half* __restrict__ fbase, int row0, int lane,
                         unsigned (&A)[4][4]){
    int g = lane >> 2, t2 = (lane & 3) * 2;
    int ra = row0 + g;
    #pragma unroll
    for (int kt = 0; kt < KT; kt++){
        const half* p0 = fbase + ra*40 + kt*16 + t2;
        const half* p1 = fbase + (ra + 8)*40 + kt*16 + t2;
        A[kt][0] = *reinterpret_cast<const unsigned*>(p0);
        A[kt][1] = *reinterpret_cast<const unsigned*>(p1);
        A[kt][2] = *reinterpret_cast<const unsigned*>(p0 + 8);
        A[kt][3] = *reinterpret_cast<const unsigned*>(p1 + 8);
    }
}

// stage weights into per-lane fragment order, fp16 hi/lo packed per uint4
DI void stage(char* sm, int off, const float* __restrict__ w,
              int Kreal, int Nreal, int ldw, int KT, int NTI, int tid){
    uint4* fq = reinterpret_cast<uint4*>(sm + off);
    int total = NTI * KT * 32;
    for (int idx = tid; idx < total; idx += NT){
        int lane = idx & 31;
        int kt   = (idx >> 5) % KT;
        int nt   = idx / (32 * KT);
        int n  = nt*8 + (lane >> 2);
        int k0 = kt*16 + (lane & 3)*2;
        float v[4];
        #pragma unroll
        for (int q = 0; q < 4; q++){
            int k = k0 + (q >> 1)*8 + (q & 1);
            v[q] = (k < Kreal && n < Nreal) ? w[k*ldw + n] : 0.0f;
        }
        unsigned hx, lx, hy, ly;
        split2s(v[0], v[1], hx, lx);
        split2s(v[2], v[3], hy, ly);
        fq[idx] = make_uint4(hx, hy, lx, ly);
    }
}

// ---------------- main fused kernel ----------------
__global__ void __launch_bounds__(NT, 3)
stress_hmma_kernel(const float* __restrict__ Fg, const float* __restrict__ Cg,
                   const float* __restrict__ w1, const float* __restrict__ b1,
                   const float* __restrict__ w2, const float* __restrict__ b2,
                   const float* __restrict__ w3, const float* __restrict__ b3,
                   const float* __restrict__ w4, const float* __restrict__ b4,
                   const float* __restrict__ w5, const float* __restrict__ b5,
                   const float* __restrict__ tlw, const int* __restrict__ traj_ids,
                   float* __restrict__ outg, int B)
{
    extern __shared__ __align__(16) char sm[];
    const int tid   = threadIdx.x;
    const int lane  = tid & 31;
    const int mrow0 = (tid >> 5) * 16;      // warp's m-tile base row (8 warps x 16 rows)
    const bool isPolar = (tid < TILE);      // warps 0-3: polar+epilogue; warps 4-7: features
    const int  item    = isPolar ? tid : (tid - TILE);

    // ---- stage weight fragments (once) ----
    stage(sm, O_WF1, w1, 25, 64, 64, 2, 8, tid);
    stage(sm, O_WF2, w2, 64, 64, 64, 4, 8, tid);
    stage(sm, O_WF3, w3, 64, 64, 64, 4, 8, tid);
    stage(sm, O_WF4, w4, 64, 64, 64, 4, 8, tid);
    stage(sm, O_WF5, w5, 64,  9,  9, 4, 2, tid);

    // ---- biases; fold constant latent into b1 ----
    float* sb = reinterpret_cast<float*>(sm + O_BIAS);
    if (tid < 64){
        int t = traj_ids[0];
        float a = b1[tid];
        #pragma unroll
        for (int e = 0; e < 32; e++)
            a = fmaf(tlw[t*32 + e], w1[(25+e)*64 + tid], a);
        sb[tid]       = a;
        sb[64  + tid] = b2[tid];
        sb[128 + tid] = b3[tid];
        sb[192 + tid] = b4[tid];
    }
    if (tid < 16) sb[256 + tid] = (tid < 9) ? b5[tid] : 0.0f;
    __syncthreads();

    half*  fB   = reinterpret_cast<half*>(sm + O_FEAT);   // 128 rows x 40 halves
    float* outS = reinterpret_cast<float*>(sm + O_OUTS);  // 128 rows x 9 floats (disjoint)
    int*   ctrS = reinterpret_cast<int*>(sm + O_CTR);

    const uint4* WF1 = (const uint4*)(sm + O_WF1);
    const uint4* WF2 = (const uint4*)(sm + O_WF2);
    const uint4* WF3 = (const uint4*)(sm + O_WF3);
    const uint4* WF4 = (const uint4*)(sm + O_WF4);
    const uint4* WF5 = (const uint4*)(sm + O_WF5);

    const int tiles = (B + TILE - 1) / TILE;
    int myTile = blockIdx.x;

    while (myTile < tiles){
        const int  i  = myTile * TILE + item;
        const bool ok = (i < B);

        float f[9];
        float R0=1,R1=0,R2=0,R3=0,R4=1,R5=0,R6=0,R7=0,R8=1;

        // ---- load F (identity if OOB); both halves need it ----
        if (ok){
            #pragma unroll
            for (int a = 0; a < 9; a++) f[a] = Fg[(size_t)i*9 + a];
        } else {
            #pragma unroll
            for (int a = 0; a < 9; a++) f[a] = (a % 4 == 0) ? 1.0f : 0.0f;
        }

        if (isPolar){
            // ---- polar rotation: Newton X <- 0.5(X + X^-T), 6 iters ----
            R0=f[0];R1=f[1];R2=f[2];R3=f[3];R4=f[4];R5=f[5];R6=f[6];R7=f[7];R8=f[8];
            #pragma unroll 1
            for (int it = 0; it < 6; it++){
                float C00 = R4*R8 - R5*R7, C01 = R5*R6 - R3*R8, C02 = R3*R7 - R4*R6;
                float C10 = R2*R7 - R1*R8, C11 = R0*R8 - R2*R6, C12 = R1*R6 - R0*R7;
                float C20 = R1*R5 - R2*R4, C21 = R2*R3 - R0*R5, C22 = R0*R4 - R1*R3;
                float dR  = R0*C00 + R1*C01 + R2*C02;
                float hd  = 0.5f * rcp_a(dR);
                R0 = 0.5f*R0 + C00*hd; R1 = 0.5f*R1 + C01*hd; R2 = 0.5f*R2 + C02*hd;
                R3 = 0.5f*R3 + C10*hd; R4 = 0.5f*R4 + C11*hd; R5 = 0.5f*R5 + C12*hd;
                R6 = 0.5f*R6 + C20*hd; R7 = 0.5f*R7 + C21*hd; R8 = 0.5f*R8 + C22*hd;
            }
        } else {
            // ---- features for item = tid-128 ----
            float t00 = f[0]*f[0] + f[3]*f[3] + f[6]*f[6];
            float t01 = f[0]*f[1] + f[3]*f[4] + f[6]*f[7];
            float t02 = f[0]*f[2] + f[3]*f[5] + f[6]*f[8];
            float t11 = f[1]*f[1] + f[4]*f[4] + f[7]*f[7];
            float t12 = f[1]*f[2] + f[4]*f[5] + f[7]*f[8];
            float t22 = f[2]*f[2] + f[5]*f[5] + f[8]*f[8];

            float det = f[0]*(f[4]*f[8]-f[5]*f[7])
                      + f[1]*(f[5]*f[6]-f[3]*f[8])
                      + f[2]*(f[3]*f[7]-f[4]*f[6]);
            float dcl = (det < 0.0f) ? 1e-9f : det;

            float q  = (t00 + t11 + t22) * (1.0f/3.0f);
            float p1 = t01*t01 + t02*t02 + t12*t12;
            float m0 = t00 - q, m1 = t11 - q, m2 = t22 - q;
            float p2 = m0*m0 + m1*m1 + m2*m2 + 2.0f*p1;
            float p  = sqrt_a(p2 * (1.0f/6.0f) + 1e-30f);
            float ip = rcp_a(p);
            float b00 = m0*ip, b11 = m1*ip, b22 = m2*ip;
            float c01 = t01*ip, c02 = t02*ip, c12 = t12*ip;
            float detB = b00*(b11*b22 - c12*c12)
                       - c01*(c01*b22 - c12*c02)
                       + c02*(c01*c12 - b11*c02);
            float r = fminf(1.0f, fmaxf(-1.0f, 0.5f*detB));
            float phi = acosf(r) * (1.0f/3.0f);
            float e1 = q + 2.0f*p*__cosf(phi);
            float e3 = q + 2.0f*p*__cosf(phi + 2.0943951023931953f);
            float e2 = 3.0f*q - e1 - e3;
            float s1 = sqrt_a(fmaxf(e1, 0.0f));
            float s2 = sqrt_a(fmaxf(e2, 0.0f));
            float s3 = sqrt_a(fmaxf(e3, 0.0f));

            float F00c = fmaxf(f[0], 1e-6f);

            float ft[32];
            ft[0]=s1; ft[1]=s2; ft[2]=s3;
            ft[3]=t00; ft[4]=t01; ft[5]=t02;
            ft[6]=t01; ft[7]=t11; ft[8]=t12;
            ft[9]=t02; ft[10]=t12; ft[11]=t22;
            ft[12]=dcl; ft[13]=__logf(dcl);
            ft[14]=F00c; ft[15]=__logf(F00c);
            #pragma unroll
            for (int a = 0; a < 9; a++)
                ft[16+a] = ok ? Cg[(size_t)i*9 + a] : 0.0f;
            #pragma unroll
            for (int a = 25; a < 32; a++) ft[a] = 0.0f;

            unsigned* wrow = reinterpret_cast<unsigned*>(fB + item*40);
            #pragma unroll
            for (int c = 0; c < 16; c++){
                __half2 hv = __floats2half2_rn(ft[2*c], ft[2*c+1]);
                wrow[c] = *reinterpret_cast<unsigned*>(&hv);
            }
        }
        __syncthreads();                       // S1: features visible

        // grab next tile early; published at S3
        if (tid == 0) *ctrS = atomicAdd(&g_tile_ctr, 1);

        float acc[8][4];
        unsigned Ah[4][4];

        load_feat_frags1<2>(fB, mrow0, lane, Ah);

        // ---- MLP on HMMA (2-product: Ah*Bh + Ah*Bl) ----
        init_acc1<8>(acc, sb, lane);
        mma_block1<2,8>(acc, Ah, WF1, lane);
        act_frags1(acc, Ah);

        init_acc1<8>(acc, sb + 64, lane);
        mma_block1<4,8>(acc, Ah, WF2, lane);
        act_frags1(acc, Ah);

        init_acc1<8>(acc, sb + 128, lane);
        mma_block1<4,8>(acc, Ah, WF3, lane);
        act_frags1(acc, Ah);

        init_acc1<8>(acc, sb + 192, lane);
        mma_block1<4,8>(acc, Ah, WF4, lane);
        act_frags1(acc, Ah);

        init_acc1<2>(acc, sb + 256, lane);
        mma_block1<4,2>(acc, Ah, WF5, lane);

        // ---- scatter layer-5 D (only cols 0..8 are consumed) ----
        {
            int g = lane >> 2, t2 = (lane & 3) * 2;
            int row = mrow0 + g;
            outS[row*9 + t2]         = acc[0][0];
            outS[row*9 + t2 + 1]     = acc[0][1];
            outS[(row+8)*9 + t2]     = acc[0][2];
            outS[(row+8)*9 + t2 + 1] = acc[0][3];
            if ((lane & 3) == 0){
                outS[row*9 + 8]     = acc[1][0];
                outS[(row+8)*9 + 8] = acc[1][2];
            }
        }
        __syncthreads();                       // S3: outS + next-tile slot visible

        int nextTile = *ctrS;

        // Epilogue (warps 0-3) overlaps the next tile's feature phase (warps 4-7):
        // outS is disjoint from fB, so no further barrier is needed.
        if (isPolar && ok){
            float o[9];
            #pragma unroll
            for (int c = 0; c < 9; c++) o[c] = outS[item*9 + c];

            // ---- epilogue: sym, P = R*S, cauchy = P*F^T ----
            float s00 = o[0], s01 = 0.5f*(o[1]+o[3]), s02 = 0.5f*(o[2]+o[6]);
            float s11 = o[4], s12 = 0.5f*(o[5]+o[7]), s22 = o[8];

            float P00 = R0*s00 + R1*s01 + R2*s02;
            float P01 = R0*s01 + R1*s11 + R2*s12;
            float P02 = R0*s02 + R1*s12 + R2*s22;
            float P10 = R3*s00 + R4*s01 + R5*s02;
            float P11 = R3*s01 + R4*s11 + R5*s12;
            float P12 = R3*s02 + R4*s12 + R5*s22;
            float P20 = R6*s00 + R7*s01 + R8*s02;
            float P21 = R6*s01 + R7*s11 + R8*s12;
            float P22 = R6*s02 + R7*s12 + R8*s22;

            size_t o9 = (size_t)i*9;
            outg[o9+0] = P00*f[0] + P01*f[1] + P02*f[2];
            outg[o9+1] = P00*f[3] + P01*f[4] + P02*f[5];
            outg[o9+2] = P00*f[6] + P01*f[7] + P02*f[8];
            outg[o9+3] = P10*f[0] + P11*f[1] + P12*f[2];
            outg[o9+4] = P10*f[3] + P11*f[4] + P12*f[5];
            outg[o9+5] = P10*f[6] + P11*f[7] + P12*f[8];
            outg[o9+6] = P20*f[0] + P21*f[1] + P22*f[2];
            outg[o9+7] = P20*f[3] + P21*f[4] + P22*f[5];
            outg[o9+8] = P20*f[6] + P21*f[7] + P22*f[8];
        }

        myTile = nextTile;
    }
}

// ---------------- launch ----------------
extern "C" void kernel_launch(void* const* d_in, const int* in_sizes, int n_in,
                              void* d_out, int out_size)
{
    const float* F   = (const float*)d_in[0];
    const float* C   = (const float*)d_in[1];
    const float* w1  = (const float*)d_in[2];
    const float* b1  = (const float*)d_in[3];
    const float* w2  = (const float*)d_in[4];
    const float* b2  = (const float*)d_in[5];
    const float* w3  = (const float*)d_in[6];
    const float* b3  = (const float*)d_in[7];
    const float* w4  = (const float*)d_in[8];
    const float* b4  = (const float*)d_in[9];
    const float* w5  = (const float*)d_in[10];
    const float* b5  = (const float*)d_in[11];
    const float* tlw = (const float*)d_in[12];
    const int*   tid = (const int*)d_in[13];
    float* out = (float*)d_out;

    int B = in_sizes[0] / 9;
    cudaFuncSetAttribute(stress_hmma_kernel,
                         cudaFuncAttributeMaxDynamicSharedMemorySize, SMEM_BYTES);

    int tiles = (B + TILE - 1) / TILE;
    int grid = tiles < 444 ? tiles : 444;   // 148 SMs x 3 CTAs

    reset_ctr_kernel<<<1, 1>>>(grid);       // counter starts past the static seeds
    stress_hmma_kernel<<<grid, NT, SMEM_BYTES>>>(
        F, C, w1, b1, w2, b2, w3, b3, w4, b4, w5, b5, tlw, tid, out, B);
}

// round 14
// speedup vs baseline: 1.0815x; 1.0815x over previous
#include <cuda_runtime.h>
#include <cuda_fp16.h>
#include <cstdint>

#define DI __device__ __forceinline__
typedef unsigned long long ull;

constexpr int NT   = 256;  // 8 warps; warp w owns m-tile rows [16w, 16w+16)
constexpr int TILE = 128;  // items per CTA-tile

// ---------------- smem layout (bytes) ----------------
// Weight fragments: per layer, [ntile][ktile][lane] -> uint4 {bh.x,bh.y,bl.x,bl.y}
constexpr int O_WF1  = 0;        // 8*2*32*16 = 8192
constexpr int O_WF2  = 8192;     // 8*4*32*16 = 16384
constexpr int O_WF3  = 24576;    // 16384
constexpr int O_WF4  = 40960;    // 16384
constexpr int O_WF5  = 57344;    // 2*4*32*16 = 4096  (ends 61440)
constexpr int O_BIAS = 61440;    // 272 floats = 1088 (ends 62528)
constexpr int O_FEAT = 62528;    // 128 rows * 40 halves * 2B = 10240 (feat / outS multiplexed)
constexpr int O_CTR  = 72768;    // 16 B (next-tile broadcast slot)
constexpr int SMEM_BYTES = 72784;   // fits 3 CTAs/SM (<= ~73.7 KB per CTA)

// ---------------- persistent work counter ----------------
__device__ int g_tile_ctr;
__global__ void reset_ctr_kernel(int v){ g_tile_ctr = v; }

// ---------------- packed f32x2 helpers ----------------
DI ull pack2(float x, float y){
    ull v;
    asm("mov.b64 %0, {%1,%2};" : "=l"(v)
        : "r"(__float_as_uint(x)), "r"(__float_as_uint(y)));
    return v;
}
DI float2 unpack2(ull v){
    unsigned lo, hi;
    asm("mov.b64 {%0,%1}, %2;" : "=r"(lo), "=r"(hi) : "l"(v));
    return make_float2(__uint_as_float(lo), __uint_as_float(hi));
}
DI ull mul2(ull a, ull b){ ull d; asm("mul.rn.f32x2 %0,%1,%2;" : "=l"(d) : "l"(a), "l"(b)); return d; }
DI ull add2(ull a, ull b){ ull d; asm("add.rn.f32x2 %0,%1,%2;" : "=l"(d) : "l"(a), "l"(b)); return d; }
DI ull fma2(ull a, ull b, ull c){ ull d; asm("fma.rn.f32x2 %0,%1,%2,%3;" : "=l"(d) : "l"(a), "l"(b), "l"(c)); return d; }
DI float rcp_a(float x){ float r; asm("rcp.approx.f32 %0,%1;" : "=f"(r) : "f"(x)); return r; }
DI float ex2_a(float x){ float r; asm("ex2.approx.f32 %0,%1;" : "=f"(r) : "f"(x)); return r; }
DI float sqrt_a(float x){ float r; asm("sqrt.approx.f32 %0,%1;" : "=f"(r) : "f"(x)); return r; }
DI ull dup2(float c){ unsigned u = __float_as_uint(c); return ((ull)u << 32) | u; }

// packed exact-GELU, restructured, 3-term A&S 7.1.25 erf (|err| <= 2.5e-5):
//   gelu(x) = 0.5(x+|x|) - 0.5|x|*pl(t)*e^{-x^2/2},  t = 1/(1 + p*|x|/sqrt2)
DI ull gelu2(ull x){
    const ull C_PC  = dup2(0.33272437f);      // 0.47047 / sqrt(2)
    const ull C_ONE = dup2(1.0f);
    const ull C_A3  = dup2(0.7478556f);
    const ull C_A2  = dup2(-0.0958798f);
    const ull C_A1  = dup2(0.3480242f);
    const ull C_ME  = dup2(-0.72134752044f);  // -log2(e)/2
    const ull C_H   = dup2(0.5f);
    const ull C_NH  = dup2(-0.5f);

    ull ax = x & 0x7FFFFFFF7FFFFFFFull;
    ull w  = fma2(ax, C_PC, C_ONE);
    float2 wf = unpack2(w);
    ull t  = pack2(rcp_a(wf.x), rcp_a(wf.y));
    ull pl = fma2(t, C_A3, C_A2);
    pl = fma2(t, pl, C_A1);
    pl = mul2(pl, t);
    ull x2 = mul2(x, x);
    ull mm = mul2(x2, C_ME);
    float2 mf = unpack2(mm);
    ull e  = pack2(ex2_a(mf.x), ex2_a(mf.y));
    ull pe = mul2(pl, e);
    pe = mul2(pe, ax);
    ull u = mul2(add2(x, ax), C_H);
    return fma2(pe, C_NH, u);
}

// packed f32 pair -> f16x2
DI unsigned cvt_h2(ull g){
    float2 gf = unpack2(g);
    unsigned h2;
    asm("cvt.rn.f16x2.f32 %0, %1, %2;" : "=r"(h2) : "f"(gf.y), "f"(gf.x));
    return h2;
}

DI void split2s(float v0, float v1, unsigned &hi, unsigned &lo){
    half h0 = __float2half_rn(v0), h1 = __float2half_rn(v1);
    half l0 = __float2half_rn(v0 - __half2float(h0));
    half l1 = __float2half_rn(v1 - __half2float(h1));
    hi = ((unsigned)__half_as_ushort(h1) << 16) | (unsigned)__half_as_ushort(h0);
    lo = ((unsigned)__half_as_ushort(l1) << 16) | (unsigned)__half_as_ushort(l0);
}

DI void mma16816(float (&c)[4], const unsigned (&a)[4], unsigned b0, unsigned b1){
    asm volatile(
        "mma.sync.aligned.m16n8k16.row.col.f32.f16.f16.f32 "
        "{%0,%1,%2,%3}, {%4,%5,%6,%7}, {%8,%9}, {%0,%1,%2,%3};"
        : "+f"(c[0]), "+f"(c[1]), "+f"(c[2]), "+f"(c[3])
        : "r"(a[0]), "r"(a[1]), "r"(a[2]), "r"(a[3]), "r"(b0), "r"(b1));
}

template<int NTI>
DI void init_acc1(float (&acc)[8][4], const float* bias, int lane){
    int t2 = (lane & 3) * 2;
    #pragma unroll
    for (int j = 0; j < NTI; j++){
        float2 b2v = *reinterpret_cast<const float2*>(bias + j*8 + t2);
        acc[j][0] = b2v.x; acc[j][1] = b2v.y;
        acc[j][2] = b2v.x; acc[j][3] = b2v.y;
    }
}

// one layer (single m-tile): Ah*Bh + Ah*Bl  (weights hi/lo packed in one uint4)
template<int KT, int NTI>
DI void mma_block1(float (&acc)[8][4],
                   const unsigned (&Ah)[4][4],
                   const uint4* __restrict__ wf, int lane){
    #pragma unroll
    for (int kt = 0; kt < KT; kt++){
        #pragma unroll
        for (int j = 0; j < NTI; j++){
            uint4 w = wf[(j*KT + kt)*32 + lane];
            mma16816(acc[j], Ah[kt], w.x, w.y);
            mma16816(acc[j], Ah[kt], w.z, w.w);
        }
    }
}

// D -> packed GELU -> next-layer A fragments (registers only)
DI void act_frags1(const float (&acc)[8][4], unsigned (&Ah)[4][4]){
    #pragma unroll
    for (int kk = 0; kk < 4; kk++)
    #pragma unroll
    for (int part = 0; part < 2; part++)
    #pragma unroll
    for (int pair = 0; pair < 2; pair++){
        int j = 2*kk + part;
        ull g = gelu2(pack2(acc[j][2*pair], acc[j][2*pair + 1]));
        Ah[kk][part*2 + pair] = cvt_h2(g);
    }
}

// A fragments for one 16-row m-tile from feature smem (row stride 40 halves)
template<int KT>
DI void load_feat_frags1(const half* __restrict__ fbase, int row0, int lane,
                         unsigned (&A)[4][4]){
    int g = lane >> 2, t2 = (lane & 3) * 2;
    int ra = row0 + g;
    #pragma unroll
    for (int kt = 0; kt < KT; kt++){
        const half* p0 = fbase + ra*40 + kt*16 + t2;
        const half* p1 = fbase + (ra + 8)*40 + kt*16 + t2;
        A[kt][0] = *reinterpret_cast<const unsigned*>(p0);
        A[kt][1] = *reinterpret_cast<const unsigned*>(p1);
        A[kt][2] = *reinterpret_cast<const unsigned*>(p0 + 8);
        A[kt][3] = *reinterpret_cast<const unsigned*>(p1 + 8);
    }
}

// stage weights into per-lane fragment order, fp16 hi/lo packed per uint4
DI void stage(char* sm, int off, const float* __restrict__ w,
              int Kreal, int Nreal, int ldw, int KT, int NTI, int tid){
    uint4* fq = reinterpret_cast<uint4*>(sm + off);
    int total = NTI * KT * 32;
    for (int idx = tid; idx < total; idx += NT){
        int lane = idx & 31;
        int kt   = (idx >> 5) % KT;
        int nt   = idx / (32 * KT);
        int n  = nt*8 + (lane >> 2);
        int k0 = kt*16 + (lane & 3)*2;
        float v[4];
        #pragma unroll
        for (int q = 0; q < 4; q++){
            int k = k0 + (q >> 1)*8 + (q & 1);
            v[q] = (k < Kreal && n < Nreal) ? w[k*ldw + n] : 0.0f;
        }
        unsigned hx, lx, hy, ly;
        split2s(v[0], v[1], hx, lx);
        split2s(v[2], v[3], hy, ly);
        fq[idx] = make_uint4(hx, hy, lx, ly);
    }
}

// ---------------- main fused kernel ----------------
__global__ void __launch_bounds__(NT, 3)
stress_hmma_kernel(const float* __restrict__ Fg, const float* __restrict__ Cg,
                   const float* __restrict__ w1, const float* __restrict__ b1,
                   const float* __restrict__ w2, const float* __restrict__ b2,
                   const float* __restrict__ w3, const float* __restrict__ b3,
                   const float* __restrict__ w4, const float* __restrict__ b4,
                   const float* __restrict__ w5, const float* __restrict__ b5,
                   const float* __restrict__ tlw, const int* __restrict__ traj_ids,
                   float* __restrict__ outg, int B)
{
    extern __shared__ __align__(16) char sm[];
    const int tid   = threadIdx.x;
    const int lane  = tid & 31;
    const int mrow0 = (tid >> 5) * 16;      // warp's m-tile base row (8 warps x 16 rows)
    const bool isPolar = (tid < TILE);      // warps 0-3: polar+epilogue; warps 4-7: features
    const int  item    = isPolar ? tid : (tid - TILE);

    // ---- stage weight fragments (once) ----
    stage(sm, O_WF1, w1, 25, 64, 64, 2, 8, tid);
    stage(sm, O_WF2, w2, 64, 64, 64, 4, 8, tid);
    stage(sm, O_WF3, w3, 64, 64, 64, 4, 8, tid);
    stage(sm, O_WF4, w4, 64, 64, 64, 4, 8, tid);
    stage(sm, O_WF5, w5, 64,  9,  9, 4, 2, tid);

    // ---- biases; fold constant latent into b1 ----
    float* sb = reinterpret_cast<float*>(sm + O_BIAS);
    if (tid < 64){
        int t = traj_ids[0];
        float a = b1[tid];
        #pragma unroll
        for (int e = 0; e < 32; e++)
            a = fmaf(tlw[t*32 + e], w1[(25+e)*64 + tid], a);
        sb[tid]       = a;
        sb[64  + tid] = b2[tid];
        sb[128 + tid] = b3[tid];
        sb[192 + tid] = b4[tid];
    }
    if (tid < 16) sb[256 + tid] = (tid < 9) ? b5[tid] : 0.0f;
    __syncthreads();

    half*  fB   = reinterpret_cast<half*>(sm + O_FEAT);   // 128 rows x 40 halves
    float* outS = reinterpret_cast<float*>(sm + O_FEAT);  // alias: 128 rows x 20 floats
    int*   ctrS = reinterpret_cast<int*>(sm + O_CTR);     // dedicated slot (no alias)

    const uint4* WF1 = (const uint4*)(sm + O_WF1);
    const uint4* WF2 = (const uint4*)(sm + O_WF2);
    const uint4* WF3 = (const uint4*)(sm + O_WF3);
    const uint4* WF4 = (const uint4*)(sm + O_WF4);
    const uint4* WF5 = (const uint4*)(sm + O_WF5);

    const int tiles = (B + TILE - 1) / TILE;
    int myTile = blockIdx.x;

    while (myTile < tiles){
        const int  i  = myTile * TILE + item;
        const bool ok = (i < B);

        float f[9];
        float R0=1,R1=0,R2=0,R3=0,R4=1,R5=0,R6=0,R7=0,R8=1;

        // ---- load F (identity if OOB); both halves need it ----
        if (ok){
            #pragma unroll
            for (int a = 0; a < 9; a++) f[a] = Fg[(size_t)i*9 + a];
        } else {
            #pragma unroll
            for (int a = 0; a < 9; a++) f[a] = (a % 4 == 0) ? 1.0f : 0.0f;
        }

        if (isPolar){
            // ---- polar rotation: Newton X <- 0.5(X + X^-T), 6 iters ----
            R0=f[0];R1=f[1];R2=f[2];R3=f[3];R4=f[4];R5=f[5];R6=f[6];R7=f[7];R8=f[8];
            #pragma unroll 1
            for (int it = 0; it < 6; it++){
                float C00 = R4*R8 - R5*R7, C01 = R5*R6 - R3*R8, C02 = R3*R7 - R4*R6;
                float C10 = R2*R7 - R1*R8, C11 = R0*R8 - R2*R6, C12 = R1*R6 - R0*R7;
                float C20 = R1*R5 - R2*R4, C21 = R2*R3 - R0*R5, C22 = R0*R4 - R1*R3;
                float dR  = R0*C00 + R1*C01 + R2*C02;
                float hd  = 0.5f * rcp_a(dR);
                R0 = 0.5f*R0 + C00*hd; R1 = 0.5f*R1 + C01*hd; R2 = 0.5f*R2 + C02*hd;
                R3 = 0.5f*R3 + C10*hd; R4 = 0.5f*R4 + C11*hd; R5 = 0.5f*R5 + C12*hd;
                R6 = 0.5f*R6 + C20*hd; R7 = 0.5f*R7 + C21*hd; R8 = 0.5f*R8 + C22*hd;
            }
        } else {
            // ---- features for item = tid-128 ----
            float t00 = f[0]*f[0] + f[3]*f[3] + f[6]*f[6];
            float t01 = f[0]*f[1] + f[3]*f[4] + f[6]*f[7];
            float t02 = f[0]*f[2] + f[3]*f[5] + f[6]*f[8];
            float t11 = f[1]*f[1] + f[4]*f[4] + f[7]*f[7];
            float t12 = f[1]*f[2] + f[4]*f[5] + f[7]*f[8];
            float t22 = f[2]*f[2] + f[5]*f[5] + f[8]*f[8];

            float det = f[0]*(f[4]*f[8]-f[5]*f[7])
                      + f[1]*(f[5]*f[6]-f[3]*f[8])
                      + f[2]*(f[3]*f[7]-f[4]*f[6]);
            float dcl = (det < 0.0f) ? 1e-9f : det;

            float q  = (t00 + t11 + t22) * (1.0f/3.0f);
            float p1 = t01*t01 + t02*t02 + t12*t12;
            float m0 = t00 - q, m1 = t11 - q, m2 = t22 - q;
            float p2 = m0*m0 + m1*m1 + m2*m2 + 2.0f*p1;
            float p  = sqrt_a(p2 * (1.0f/6.0f) + 1e-30f);
            float ip = rcp_a(p);
            float b00 = m0*ip, b11 = m1*ip, b22 = m2*ip;
            float c01 = t01*ip, c02 = t02*ip, c12 = t12*ip;
            float detB = b00*(b11*b22 - c12*c12)
                       - c01*(c01*b22 - c12*c02)
                       + c02*(c01*c12 - b11*c02);
            float r = fminf(1.0f, fmaxf(-1.0f, 0.5f*detB));
            float phi = acosf(r) * (1.0f/3.0f);
            float e1 = q + 2.0f*p*__cosf(phi);
            float e3 = q + 2.0f*p*__cosf(phi + 2.0943951023931953f);
            float e2 = 3.0f*q - e1 - e3;
            float s1 = sqrt_a(fmaxf(e1, 0.0f));
            float s2 = sqrt_a(fmaxf(e2, 0.0f));
            float s3 = sqrt_a(fmaxf(e3, 0.0f));

            float F00c = fmaxf(f[0], 1e-6f);

            float ft[32];
            ft[0]=s1; ft[1]=s2; ft[2]=s3;
            ft[3]=t00; ft[4]=t01; ft[5]=t02;
            ft[6]=t01; ft[7]=t11; ft[8]=t12;
            ft[9]=t02; ft[10]=t12; ft[11]=t22;
            ft[12]=dcl; ft[13]=__logf(dcl);
            ft[14]=F00c; ft[15]=__logf(F00c);
            #pragma unroll
            for (int a = 0; a < 9; a++)
                ft[16+a] = ok ? Cg[(size_t)i*9 + a] : 0.0f;
            #pragma unroll
            for (int a = 25; a < 32; a++) ft[a] = 0.0f;

            unsigned* wrow = reinterpret_cast<unsigned*>(fB + item*40);
            #pragma unroll
            for (int c = 0; c < 16; c++){
                __half2 hv = __floats2half2_rn(ft[2*c], ft[2*c+1]);
                wrow[c] = *reinterpret_cast<unsigned*>(&hv);
            }
        }
        __syncthreads();                       // S1: features visible

        // grab next tile early; published at S3 (dedicated slot, no alias)
        if (tid == 0) *ctrS = atomicAdd(&g_tile_ctr, 1);

        float acc[8][4];
        unsigned Ah[4][4];

        load_feat_frags1<2>(fB, mrow0, lane, Ah);

        // ---- MLP on HMMA (2-product: Ah*Bh + Ah*Bl) ----
        init_acc1<8>(acc, sb, lane);
        mma_block1<2,8>(acc, Ah, WF1, lane);
        act_frags1(acc, Ah);

        init_acc1<8>(acc, sb + 64, lane);
        mma_block1<4,8>(acc, Ah, WF2, lane);
        act_frags1(acc, Ah);

        init_acc1<8>(acc, sb + 128, lane);
        mma_block1<4,8>(acc, Ah, WF3, lane);
        act_frags1(acc, Ah);

        init_acc1<8>(acc, sb + 192, lane);
        mma_block1<4,8>(acc, Ah, WF4, lane);
        act_frags1(acc, Ah);

        init_acc1<2>(acc, sb + 256, lane);
        mma_block1<4,2>(acc, Ah, WF5, lane);

        __syncthreads();                       // S2: all fB reads done before overwrite

        // ---- scatter layer-5 D to staging (aliases fB) ----
        {
            int g = lane >> 2, t2 = (lane & 3) * 2;
            int row = mrow0 + g;
            #pragma unroll
            for (int j = 0; j < 2; j++){
                int col = j*8 + t2;
                outS[row*20 + col]       = acc[j][0];
                outS[row*20 + col + 1]   = acc[j][1];
                outS[(row+8)*20 + col]   = acc[j][2];
                outS[(row+8)*20 + col+1] = acc[j][3];
            }
        }
        __syncthreads();                       // S3: outS + next-tile slot visible

        int nextTile = *ctrS;

        if (isPolar && ok){
            float o[9];
            #pragma unroll
            for (int c = 0; c < 9; c++) o[c] = outS[item*20 + c];

            // ---- epilogue: sym, P = R*S, cauchy = P*F^T ----
            float s00 = o[0], s01 = 0.5f*(o[1]+o[3]), s02 = 0.5f*(o[2]+o[6]);
            float s11 = o[4], s12 = 0.5f*(o[5]+o[7]), s22 = o[8];

            float P00 = R0*s00 + R1*s01 + R2*s02;
            float P01 = R0*s01 + R1*s11 + R2*s12;
            float P02 = R0*s02 + R1*s12 + R2*s22;
            float P10 = R3*s00 + R4*s01 + R5*s02;
            float P11 = R3*s01 + R4*s11 + R5*s12;
            float P12 = R3*s02 + R4*s12 + R5*s22;
            float P20 = R6*s00 + R7*s01 + R8*s02;
            float P21 = R6*s01 + R7*s11 + R8*s12;
            float P22 = R6*s02 + R7*s12 + R8*s22;

            size_t o9 = (size_t)i*9;
            outg[o9+0] = P00*f[0] + P01*f[1] + P02*f[2];
            outg[o9+1] = P00*f[3] + P01*f[4] + P02*f[5];
            outg[o9+2] = P00*f[6] + P01*f[7] + P02*f[8];
            outg[o9+3] = P10*f[0] + P11*f[1] + P12*f[2];
            outg[o9+4] = P10*f[3] + P11*f[4] + P12*f[5];
            outg[o9+5] = P10*f[6] + P11*f[7] + P12*f[8];
            outg[o9+6] = P20*f[0] + P21*f[1] + P22*f[2];
            outg[o9+7] = P20*f[3] + P21*f[4] + P22*f[5];
            outg[o9+8] = P20*f[6] + P21*f[7] + P22*f[8];
        }

        __syncthreads();                       // S4: epilogue outS reads done before
                                               //     next iteration's feature writes
                                               //     (outS aliases fB)
        myTile = nextTile;
    }
}

// ---------------- launch ----------------
extern "C" void kernel_launch(void* const* d_in, const int* in_sizes, int n_in,
                              void* d_out, int out_size)
{
    const float* F   = (const float*)d_in[0];
    const float* C   = (const float*)d_in[1];
    const float* w1  = (const float*)d_in[2];
    const float* b1  = (const float*)d_in[3];
    const float* w2  = (const float*)d_in[4];
    const float* b2  = (const float*)d_in[5];
    const float* w3  = (const float*)d_in[6];
    const float* b3  = (const float*)d_in[7];
    const float* w4  = (const float*)d_in[8];
    const float* b4  = (const float*)d_in[9];
    const float* w5  = (const float*)d_in[10];
    const float* b5  = (const float*)d_in[11];
    const float* tlw = (const float*)d_in[12];
    const int*   tid = (const int*)d_in[13];
    float* out = (float*)d_out;

    int B = in_sizes[0] / 9;
    cudaFuncSetAttribute(stress_hmma_kernel,
                         cudaFuncAttributeMaxDynamicSharedMemorySize, SMEM_BYTES);

    int tiles = (B + TILE - 1) / TILE;
    int grid = tiles < 444 ? tiles : 444;   // 148 SMs x 3 CTAs

    reset_ctr_kernel<<<1, 1>>>(grid);       // counter starts past the static seeds
    stress_hmma_kernel<<<grid, NT, SMEM_BYTES>>>(
        F, C, w1, b1, w2, b2, w3, b3, w4, b4, w5, b5, tlw, tid, out, B);
}

// round 16
// speedup vs baseline: 1.0905x; 1.0083x over previous
#include <cuda_runtime.h>
#include <cuda_fp16.h>
#include <cstdint>

#define DI __device__ __forceinline__
typedef unsigned long long ull;

constexpr int NT   = 256;  // 8 warps; warp w owns m-tile rows [16w, 16w+16)
constexpr int TILE = 128;  // items per CTA-tile

// ---------------- smem layout (bytes) ----------------
constexpr int O_WF1  = 0;        // 8*2*32*16 = 8192
constexpr int O_WF2  = 8192;     // 8*4*32*16 = 16384
constexpr int O_WF3  = 24576;    // 16384
constexpr int O_WF4  = 40960;    // 16384
constexpr int O_WF5  = 57344;    // 2*4*32*16 = 4096  (ends 61440)
constexpr int O_BIAS = 61440;    // 272 floats = 1088 (ends 62528)
constexpr int O_FEAT = 62528;    // 128 rows * 40 halves * 2B = 10240 (feat / outS multiplexed)
constexpr int O_CTR  = 72768;    // 16 B (next-tile broadcast slot)
constexpr int SMEM_BYTES = 72784;   // fits 3 CTAs/SM

// ---------------- persistent work counter ----------------
__device__ int g_tile_ctr;
__global__ void reset_ctr_kernel(int v){ g_tile_ctr = v; }

// ---------------- packed f32x2 helpers ----------------
DI ull pack2(float x, float y){
    ull v;
    asm("mov.b64 %0, {%1,%2};" : "=l"(v)
        : "r"(__float_as_uint(x)), "r"(__float_as_uint(y)));
    return v;
}
DI float2 unpack2(ull v){
    unsigned lo, hi;
    asm("mov.b64 {%0,%1}, %2;" : "=r"(lo), "=r"(hi) : "l"(v));
    return make_float2(__uint_as_float(lo), __uint_as_float(hi));
}
DI ull mul2(ull a, ull b){ ull d; asm("mul.rn.f32x2 %0,%1,%2;" : "=l"(d) : "l"(a), "l"(b)); return d; }
DI ull add2(ull a, ull b){ ull d; asm("add.rn.f32x2 %0,%1,%2;" : "=l"(d) : "l"(a), "l"(b)); return d; }
DI ull fma2(ull a, ull b, ull c){ ull d; asm("fma.rn.f32x2 %0,%1,%2,%3;" : "=l"(d) : "l"(a), "l"(b), "l"(c)); return d; }
DI float rcp_a(float x){ float r; asm("rcp.approx.f32 %0,%1;" : "=f"(r) : "f"(x)); return r; }
DI float ex2_a(float x){ float r; asm("ex2.approx.f32 %0,%1;" : "=f"(r) : "f"(x)); return r; }
DI float sqrt_a(float x){ float r; asm("sqrt.approx.f32 %0,%1;" : "=f"(r) : "f"(x)); return r; }
DI ull dup2(float c){ unsigned u = __float_as_uint(c); return ((ull)u << 32) | u; }

// packed exact-GELU, 3-term A&S 7.1.25 erf (|erf err| <= 2.5e-5), fully folded:
//   t = 1/(1 + c|x|),  |x|t = (1-t)/c
//   gelu(x) = 0.5(x+|x|) - q(t)*2^(-x^2*log2(e)/2),
//   q(t) = (0.5/c)(1-t)(a1 + a2 t + a3 t^2)   [degree-3 Horner; q(1)=0]
DI ull gelu2(ull x){
    const ull C_PC = dup2(0.33272437f);       // 0.47047 / sqrt(2)
    const ull C_ONE= dup2(1.0f);
    const ull C_Q3 = dup2(-1.1238390f);
    const ull C_Q2 = dup2( 1.2679223f);
    const ull C_Q1 = dup2(-0.6670762f);
    const ull C_Q0 = dup2( 0.5229930f);
    const ull C_ME = dup2(-0.72134752044f);   // -log2(e)/2
    const ull C_H  = dup2(0.5f);

    ull ax = x & 0x7FFFFFFF7FFFFFFFull;
    ull w  = fma2(ax, C_PC, C_ONE);
    float2 wf = unpack2(w);
    ull t  = pack2(rcp_a(wf.x), rcp_a(wf.y));
    ull q  = fma2(t, C_Q3, C_Q2);
    q = fma2(t, q, C_Q1);
    q = fma2(t, q, C_Q0);
    ull x2 = mul2(x, x);
    ull mm = mul2(x2, C_ME);
    float2 mf = unpack2(mm);
    ull e  = pack2(ex2_a(mf.x), ex2_a(mf.y));
    ull pe = mul2(q, e);
    ull u  = mul2(add2(x, ax), C_H);          // relu(x) = 0.5(x+|x|)
    return add2(u, pe ^ 0x8000000080000000ull);
}

// packed f32 pair -> f16x2
DI unsigned cvt_h2(ull g){
    float2 gf = unpack2(g);
    unsigned h2;
    asm("cvt.rn.f16x2.f32 %0, %1, %2;" : "=r"(h2) : "f"(gf.y), "f"(gf.x));
    return h2;
}

DI void split2s(float v0, float v1, unsigned &hi, unsigned &lo){
    half h0 = __float2half_rn(v0), h1 = __float2half_rn(v1);
    half l0 = __float2half_rn(v0 - __half2float(h0));
    half l1 = __float2half_rn(v1 - __half2float(h1));
    hi = ((unsigned)__half_as_ushort(h1) << 16) | (unsigned)__half_as_ushort(h0);
    lo = ((unsigned)__half_as_ushort(l1) << 16) | (unsigned)__half_as_ushort(l0);
}

DI void mma16816(float (&c)[4], const unsigned (&a)[4], unsigned b0, unsigned b1){
    asm volatile(
        "mma.sync.aligned.m16n8k16.row.col.f32.f16.f16.f32 "
        "{%0,%1,%2,%3}, {%4,%5,%6,%7}, {%8,%9}, {%0,%1,%2,%3};"
        : "+f"(c[0]), "+f"(c[1]), "+f"(c[2]), "+f"(c[3])
        : "r"(a[0]), "r"(a[1]), "r"(a[2]), "r"(a[3]), "r"(b0), "r"(b1));
}

template<int NTI>
DI void init_acc1(float (&acc)[8][4], const float* bias, int lane){
    int t2 = (lane & 3) * 2;
    #pragma unroll
    for (int j = 0; j < NTI; j++){
        float2 b2v = *reinterpret_cast<const float2*>(bias + j*8 + t2);
        acc[j][0] = b2v.x; acc[j][1] = b2v.y;
        acc[j][2] = b2v.x; acc[j][3] = b2v.y;
    }
}

// one layer (single m-tile): Ah*Bh + Ah*Bl  (weights hi/lo packed in one uint4)
template<int KT, int NTI>
DI void mma_block1(float (&acc)[8][4],
                   const unsigned (&Ah)[4][4],
                   const uint4* __restrict__ wf, int lane){
    #pragma unroll
    for (int kt = 0; kt < KT; kt++){
        #pragma unroll
        for (int j = 0; j < NTI; j++){
            uint4 w = wf[(j*KT + kt)*32 + lane];
            mma16816(acc[j], Ah[kt], w.x, w.y);
            mma16816(acc[j], Ah[kt], w.z, w.w);
        }
    }
}

// D -> packed GELU -> next-layer A fragments (registers only)
DI void act_frags1(const float (&acc)[8][4], unsigned (&Ah)[4][4]){
    #pragma unroll
    for (int kk = 0; kk < 4; kk++)
    #pragma unroll
    for (int part = 0; part < 2; part++)
    #pragma unroll
    for (int pair = 0; pair < 2; pair++){
        int j = 2*kk + part;
        ull g = gelu2(pack2(acc[j][2*pair], acc[j][2*pair + 1]));
        Ah[kk][part*2 + pair] = cvt_h2(g);
    }
}

// A fragments for one 16-row m-tile from feature smem (row stride 40 halves)
template<int KT>
DI void load_feat_frags1(const half* __restrict__ fbase, int row0, int lane,
                         unsigned (&A)[4][4]){
    int g = lane >> 2, t2 = (lane & 3) * 2;
    int ra = row0 + g;
    #pragma unroll
    for (int kt = 0; kt < KT; kt++){
        const half* p0 = fbase + ra*40 + kt*16 + t2;
        const half* p1 = fbase + (ra + 8)*40 + kt*16 + t2;
        A[kt][0] = *reinterpret_cast<const unsigned*>(p0);
        A[kt][1] = *reinterpret_cast<const unsigned*>(p1);
        A[kt][2] = *reinterpret_cast<const unsigned*>(p0 + 8);
        A[kt][3] = *reinterpret_cast<const unsigned*>(p1 + 8);
    }
}

// stage weights into per-lane fragment order, fp16 hi/lo packed per uint4
DI void stage(char* sm, int off, const float* __restrict__ w,
              int Kreal, int Nreal, int ldw, int KT, int NTI, int tid){
    uint4* fq = reinterpret_cast<uint4*>(sm + off);
    int total = NTI * KT * 32;
    for (int idx = tid; idx < total; idx += NT){
        int lane = idx & 31;
        int kt   = (idx >> 5) % KT;
        int nt   = idx / (32 * KT);
        int n  = nt*8 + (lane >> 2);
        int k0 = kt*16 + (lane & 3)*2;
        float v[4];
        #pragma unroll
        for (int q = 0; q < 4; q++){
            int k = k0 + (q >> 1)*8 + (q & 1);
            v[q] = (k < Kreal && n < Nreal) ? w[k*ldw + n] : 0.0f;
        }
        unsigned hx, lx, hy, ly;
        split2s(v[0], v[1], hx, lx);
        split2s(v[2], v[3], hy, ly);
        fq[idx] = make_uint4(hx, hy, lx, ly);
    }
}

// ---------------- main fused kernel ----------------
__global__ void __launch_bounds__(NT, 3)
stress_hmma_kernel(const float* __restrict__ Fg, const float* __restrict__ Cg,
                   const float* __restrict__ w1, const float* __restrict__ b1,
                   const float* __restrict__ w2, const float* __restrict__ b2,
                   const float* __restrict__ w3, const float* __restrict__ b3,
                   const float* __restrict__ w4, const float* __restrict__ b4,
                   const float* __restrict__ w5, const float* __restrict__ b5,
                   const float* __restrict__ tlw, const int* __restrict__ traj_ids,
                   float* __restrict__ outg, int B)
{
    extern __shared__ __align__(16) char sm[];
    const int tid   = threadIdx.x;
    const int lane  = tid & 31;
    const int mrow0 = (tid >> 5) * 16;      // warp's m-tile base row (8 warps x 16 rows)
    const bool isPolar = (tid < TILE);      // warps 0-3: polar+epilogue; warps 4-7: features
    const int  item    = isPolar ? tid : (tid - TILE);

    // ---- stage weight fragments (once) ----
    stage(sm, O_WF1, w1, 25, 64, 64, 2, 8, tid);
    stage(sm, O_WF2, w2, 64, 64, 64, 4, 8, tid);
    stage(sm, O_WF3, w3, 64, 64, 64, 4, 8, tid);
    stage(sm, O_WF4, w4, 64, 64, 64, 4, 8, tid);
    stage(sm, O_WF5, w5, 64,  9,  9, 4, 2, tid);

    // ---- biases; fold constant latent into b1 ----
    float* sb = reinterpret_cast<float*>(sm + O_BIAS);
    if (tid < 64){
        int t = traj_ids[0];
        float a = b1[tid];
        #pragma unroll
        for (int e = 0; e < 32; e++)
            a = fmaf(tlw[t*32 + e], w1[(25+e)*64 + tid], a);
        sb[tid]       = a;
        sb[64  + tid] = b2[tid];
        sb[128 + tid] = b3[tid];
        sb[192 + tid] = b4[tid];
    }
    if (tid < 16) sb[256 + tid] = (tid < 9) ? b5[tid] : 0.0f;
    __syncthreads();

    half*  fB   = reinterpret_cast<half*>(sm + O_FEAT);   // 128 rows x 40 halves
    float* outS = reinterpret_cast<float*>(sm + O_FEAT);  // alias: 128 rows x 20 floats
    int*   ctrS = reinterpret_cast<int*>(sm + O_CTR);     // dedicated slot (no alias)

    const uint4* WF1 = (const uint4*)(sm + O_WF1);
    const uint4* WF2 = (const uint4*)(sm + O_WF2);
    const uint4* WF3 = (const uint4*)(sm + O_WF3);
    const uint4* WF4 = (const uint4*)(sm + O_WF4);
    const uint4* WF5 = (const uint4*)(sm + O_WF5);

    const int tiles = (B + TILE - 1) / TILE;
    int myTile = blockIdx.x;

    while (myTile < tiles){
        const int  i  = myTile * TILE + item;
        const bool ok = (i < B);

        float f[9];
        float R0=1,R1=0,R2=0,R3=0,R4=1,R5=0,R6=0,R7=0,R8=1;

        // ---- load F (identity if OOB); both halves need it ----
        if (ok){
            #pragma unroll
            for (int a = 0; a < 9; a++) f[a] = Fg[(size_t)i*9 + a];
        } else {
            #pragma unroll
            for (int a = 0; a < 9; a++) f[a] = (a % 4 == 0) ? 1.0f : 0.0f;
        }

        if (isPolar){
            // ---- polar rotation: Newton X <- 0.5(X + X^-T), 5 iters ----
            R0=f[0];R1=f[1];R2=f[2];R3=f[3];R4=f[4];R5=f[5];R6=f[6];R7=f[7];R8=f[8];
            #pragma unroll 1
            for (int it = 0; it < 5; it++){
                float C00 = R4*R8 - R5*R7, C01 = R5*R6 - R3*R8, C02 = R3*R7 - R4*R6;
                float C10 = R2*R7 - R1*R8, C11 = R0*R8 - R2*R6, C12 = R1*R6 - R0*R7;
                float C20 = R1*R5 - R2*R4, C21 = R2*R3 - R0*R5, C22 = R0*R4 - R1*R3;
                float dR  = R0*C00 + R1*C01 + R2*C02;
                float hd  = 0.5f * rcp_a(dR);
                R0 = 0.5f*R0 + C00*hd; R1 = 0.5f*R1 + C01*hd; R2 = 0.5f*R2 + C02*hd;
                R3 = 0.5f*R3 + C10*hd; R4 = 0.5f*R4 + C11*hd; R5 = 0.5f*R5 + C12*hd;
                R6 = 0.5f*R6 + C20*hd; R7 = 0.5f*R7 + C21*hd; R8 = 0.5f*R8 + C22*hd;
            }
        } else {
            // ---- features for item = tid-128 ----
            float t00 = f[0]*f[0] + f[3]*f[3] + f[6]*f[6];
            float t01 = f[0]*f[1] + f[3]*f[4] + f[6]*f[7];
            float t02 = f[0]*f[2] + f[3]*f[5] + f[6]*f[8];
            float t11 = f[1]*f[1] + f[4]*f[4] + f[7]*f[7];
            float t12 = f[1]*f[2] + f[4]*f[5] + f[7]*f[8];
            float t22 = f[2]*f[2] + f[5]*f[5] + f[8]*f[8];

            float det = f[0]*(f[4]*f[8]-f[5]*f[7])
                      + f[1]*(f[5]*f[6]-f[3]*f[8])
                      + f[2]*(f[3]*f[7]-f[4]*f[6]);
            float dcl = (det < 0.0f) ? 1e-9f : det;

            float q  = (t00 + t11 + t22) * (1.0f/3.0f);
            float p1 = t01*t01 + t02*t02 + t12*t12;
            float m0 = t00 - q, m1 = t11 - q, m2 = t22 - q;
            float p2 = m0*m0 + m1*m1 + m2*m2 + 2.0f*p1;
            float p  = sqrt_a(p2 * (1.0f/6.0f) + 1e-30f);
            float ip = rcp_a(p);
            float b00 = m0*ip, b11 = m1*ip, b22 = m2*ip;
            float c01 = t01*ip, c02 = t02*ip, c12 = t12*ip;
            float detB = b00*(b11*b22 - c12*c12)
                       - c01*(c01*b22 - c12*c02)
                       + c02*(c01*c12 - b11*c02);
            float r = fminf(1.0f, fmaxf(-1.0f, 0.5f*detB));

            // acos via A&S 4.4.45 poly (|err| <= 6.7e-5 rad)
            float ar  = fabsf(r);
            float srt = sqrt_a(fmaxf(1.0f - ar, 0.0f));
            float pol = fmaf(fmaf(fmaf(-0.0187293f, ar, 0.0742610f), ar,
                                  -0.2121144f), ar, 1.5707288f);
            float ac  = srt * pol;
            float aco = (r >= 0.0f) ? ac : (3.14159265358979f - ac);
            float phi = aco * (1.0f/3.0f);

            float e1 = q + 2.0f*p*__cosf(phi);
            float e3 = q + 2.0f*p*__cosf(phi + 2.0943951023931953f);
            float e2 = 3.0f*q - e1 - e3;
            float s1 = sqrt_a(fmaxf(e1, 0.0f));
            float s2 = sqrt_a(fmaxf(e2, 0.0f));
            float s3 = sqrt_a(fmaxf(e3, 0.0f));

            float F00c = fmaxf(f[0], 1e-6f);

            float ft[32];
            ft[0]=s1; ft[1]=s2; ft[2]=s3;
            ft[3]=t00; ft[4]=t01; ft[5]=t02;
            ft[6]=t01; ft[7]=t11; ft[8]=t12;
            ft[9]=t02; ft[10]=t12; ft[11]=t22;
            ft[12]=dcl; ft[13]=__logf(dcl);
            ft[14]=F00c; ft[15]=__logf(F00c);
            #pragma unroll
            for (int a = 0; a < 9; a++)
                ft[16+a] = ok ? Cg[(size_t)i*9 + a] : 0.0f;
            #pragma unroll
            for (int a = 25; a < 32; a++) ft[a] = 0.0f;

            unsigned* wrow = reinterpret_cast<unsigned*>(fB + item*40);
            #pragma unroll
            for (int c = 0; c < 16; c++){
                __half2 hv = __floats2half2_rn(ft[2*c], ft[2*c+1]);
                wrow[c] = *reinterpret_cast<unsigned*>(&hv);
            }
        }
        __syncthreads();                       // S1: features visible

        // grab next tile early; published at S3 (dedicated slot, no alias)
        if (tid == 0) *ctrS = atomicAdd(&g_tile_ctr, 1);

        float acc[8][4];
        unsigned Ah[4][4];

        load_feat_frags1<2>(fB, mrow0, lane, Ah);

        // ---- MLP on HMMA (2-product: Ah*Bh + Ah*Bl) ----
        init_acc1<8>(acc, sb, lane);
        mma_block1<2,8>(acc, Ah, WF1, lane);
        act_frags1(acc, Ah);

        init_acc1<8>(acc, sb + 64, lane);
        mma_block1<4,8>(acc, Ah, WF2, lane);
        act_frags1(acc, Ah);

        init_acc1<8>(acc, sb + 128, lane);
        mma_block1<4,8>(acc, Ah, WF3, lane);
        act_frags1(acc, Ah);

        init_acc1<8>(acc, sb + 192, lane);
        mma_block1<4,8>(acc, Ah, WF4, lane);
        act_frags1(acc, Ah);

        init_acc1<2>(acc, sb + 256, lane);
        mma_block1<4,2>(acc, Ah, WF5, lane);

        // scatter targets only this warp's own 16 rows (same rows its frag loads
        // used), so a warp-level sync suffices here.
        __syncwarp();

        // ---- scatter layer-5 D to staging (aliases fB; warp-local rows) ----
        {
            int g = lane >> 2, t2 = (lane & 3) * 2;
            int row = mrow0 + g;
            #pragma unroll
            for (int j = 0; j < 2; j++){
                int col = j*8 + t2;
                outS[row*20 + col]       = acc[j][0];
                outS[row*20 + col + 1]   = acc[j][1];
                outS[(row+8)*20 + col]   = acc[j][2];
                outS[(row+8)*20 + col+1] = acc[j][3];
            }
        }
        __syncthreads();                       // S3: outS + next-tile slot visible

        int nextTile = *ctrS;

        if (isPolar && ok){
            float o[9];
            #pragma unroll
            for (int c = 0; c < 9; c++) o[c] = outS[item*20 + c];

            // ---- epilogue: sym, P = R*S, cauchy = P*F^T ----
            float s00 = o[0], s01 = 0.5f*(o[1]+o[3]), s02 = 0.5f*(o[2]+o[6]);
            float s11 = o[4], s12 = 0.5f*(o[5]+o[7]), s22 = o[8];

            float P00 = R0*s00 + R1*s01 + R2*s02;
            float P01 = R0*s01 + R1*s11 + R2*s12;
            float P02 = R0*s02 + R1*s12 + R2*s22;
            float P10 = R3*s00 + R4*s01 + R5*s02;
            float P11 = R3*s01 + R4*s11 + R5*s12;
            float P12 = R3*s02 + R4*s12 + R5*s22;
            float P20 = R6*s00 + R7*s01 + R8*s02;
            float P21 = R6*s01 + R7*s11 + R8*s12;
            float P22 = R6*s02 + R7*s12 + R8*s22;

            size_t o9 = (size_t)i*9;
            outg[o9+0] = P00*f[0] + P01*f[1] + P02*f[2];
            outg[o9+1] = P00*f[3] + P01*f[4] + P02*f[5];
            outg[o9+2] = P00*f[6] + P01*f[7] + P02*f[8];
            outg[o9+3] = P10*f[0] + P11*f[1] + P12*f[2];
            outg[o9+4] = P10*f[3] + P11*f[4] + P12*f[5];
            outg[o9+5] = P10*f[6] + P11*f[7] + P12*f[8];
            outg[o9+6] = P20*f[0] + P21*f[1] + P22*f[2];
            outg[o9+7] = P20*f[3] + P21*f[4] + P22*f[5];
            outg[o9+8] = P20*f[6] + P21*f[7] + P22*f[8];
        }

        __syncthreads();                       // S4: epilogue outS reads done before
                                               //     next iteration's feature writes
                                               //     (outS aliases fB)
        myTile = nextTile;
    }
}

// ---------------- launch ----------------
extern "C" void kernel_launch(void* const* d_in, const int* in_sizes, int n_in,
                              void* d_out, int out_size)
{
    const float* F   = (const float*)d_in[0];
    const float* C   = (const float*)d_in[1];
    const float* w1  = (const float*)d_in[2];
    const float* b1  = (const float*)d_in[3];
    const float* w2  = (const float*)d_in[4];
    const float* b2  = (const float*)d_in[5];
    const float* w3  = (const float*)d_in[6];
    const float* b3  = (const float*)d_in[7];
    const float* w4  = (const float*)d_in[8];
    const float* b4  = (const float*)d_in[9];
    const float* w5  = (const float*)d_in[10];
    const float* b5  = (const float*)d_in[11];
    const float* tlw = (const float*)d_in[12];
    const int*   tid = (const int*)d_in[13];
    float* out = (float*)d_out;

    int B = in_sizes[0] / 9;
    cudaFuncSetAttribute(stress_hmma_kernel,
                         cudaFuncAttributeMaxDynamicSharedMemorySize, SMEM_BYTES);

    int tiles = (B + TILE - 1) / TILE;
    int grid = tiles < 444 ? tiles : 444;   // 148 SMs x 3 CTAs

    reset_ctr_kernel<<<1, 1>>>(grid);       // counter starts past the static seeds
    stress_hmma_kernel<<<grid, NT, SMEM_BYTES>>>(
        F, C, w1, b1, w2, b2, w3, b3, w4, b4, w5, b5, tlw, tid, out, B);
}

// round 17
// speedup vs baseline: 1.1065x; 1.0147x over previous
#include <cuda_runtime.h>
#include <cuda_fp16.h>
#include <cstdint>

#define DI __device__ __forceinline__
typedef unsigned long long ull;

constexpr int NT   = 256;  // 8 warps; warp w owns m-tile rows [16w, 16w+16)
constexpr int TILE = 128;  // items per CTA-tile

// ---------------- smem layout (bytes) ----------------
constexpr int O_WF1  = 0;        // 8*2*32*16 = 8192
constexpr int O_WF2  = 8192;     // 8*4*32*16 = 16384
constexpr int O_WF3  = 24576;    // 16384
constexpr int O_WF4  = 40960;    // 16384
constexpr int O_WF5  = 57344;    // 1*4*32*16 = 2048  (N=8 symmetrized; ends 59392)
constexpr int O_BIAS = 59392;    // 272 floats = 1088 (ends 60480)
constexpr int O_FEAT = 60480;    // 128 rows * 40 halves * 2B = 10240 (feat / outS multiplexed)
constexpr int O_CTR  = 70720;    // 16 B (next-tile broadcast slot)
constexpr int SMEM_BYTES = 70736;   // fits 3 CTAs/SM

// ---------------- persistent work counter ----------------
__device__ int g_tile_ctr;
__global__ void reset_ctr_kernel(int v){ g_tile_ctr = v; }

// ---------------- packed f32x2 helpers ----------------
DI ull pack2(float x, float y){
    ull v;
    asm("mov.b64 %0, {%1,%2};" : "=l"(v)
        : "r"(__float_as_uint(x)), "r"(__float_as_uint(y)));
    return v;
}
DI float2 unpack2(ull v){
    unsigned lo, hi;
    asm("mov.b64 {%0,%1}, %2;" : "=r"(lo), "=r"(hi) : "l"(v));
    return make_float2(__uint_as_float(lo), __uint_as_float(hi));
}
DI ull mul2(ull a, ull b){ ull d; asm("mul.rn.f32x2 %0,%1,%2;" : "=l"(d) : "l"(a), "l"(b)); return d; }
DI ull add2(ull a, ull b){ ull d; asm("add.rn.f32x2 %0,%1,%2;" : "=l"(d) : "l"(a), "l"(b)); return d; }
DI ull fma2(ull a, ull b, ull c){ ull d; asm("fma.rn.f32x2 %0,%1,%2,%3;" : "=l"(d) : "l"(a), "l"(b), "l"(c)); return d; }
DI float rcp_a(float x){ float r; asm("rcp.approx.f32 %0,%1;" : "=f"(r) : "f"(x)); return r; }
DI float ex2_a(float x){ float r; asm("ex2.approx.f32 %0,%1;" : "=f"(r) : "f"(x)); return r; }
DI float sqrt_a(float x){ float r; asm("sqrt.approx.f32 %0,%1;" : "=f"(r) : "f"(x)); return r; }
DI ull dup2(float c){ unsigned u = __float_as_uint(c); return ((ull)u << 32) | u; }

// packed exact-GELU, 3-term A&S 7.1.25 erf (|erf err| <= 2.5e-5), fully folded:
//   t = 1/(1 + c|x|)
//   gelu(x) = 0.5(x+|x|) + qn(t)*2^(-x^2*log2(e)/2),
//   qn(t) = -(0.5/c)(1-t)(a1 + a2 t + a3 t^2)   [sign folded into coefficients]
DI ull gelu2(ull x){
    const ull C_PC = dup2(0.33272437f);       // 0.47047 / sqrt(2)
    const ull C_ONE= dup2(1.0f);
    const ull C_Q3 = dup2( 1.1238390f);       // negated vs unfolded form
    const ull C_Q2 = dup2(-1.2679223f);
    const ull C_Q1 = dup2( 0.6670762f);
    const ull C_Q0 = dup2(-0.5229930f);
    const ull C_ME = dup2(-0.72134752044f);   // -log2(e)/2
    const ull C_H  = dup2(0.5f);

    ull ax = x & 0x7FFFFFFF7FFFFFFFull;
    ull w  = fma2(ax, C_PC, C_ONE);
    float2 wf = unpack2(w);
    ull t  = pack2(rcp_a(wf.x), rcp_a(wf.y));
    ull q  = fma2(t, C_Q3, C_Q2);
    q = fma2(t, q, C_Q1);
    q = fma2(t, q, C_Q0);
    ull x2 = mul2(x, x);
    ull mm = mul2(x2, C_ME);
    float2 mf = unpack2(mm);
    ull e  = pack2(ex2_a(mf.x), ex2_a(mf.y));
    ull pe = mul2(q, e);                      // already-negative residual
    ull u  = mul2(add2(x, ax), C_H);          // relu(x) = 0.5(x+|x|)
    return add2(u, pe);
}

// packed f32 pair -> f16x2
DI unsigned cvt_h2(ull g){
    float2 gf = unpack2(g);
    unsigned h2;
    asm("cvt.rn.f16x2.f32 %0, %1, %2;" : "=r"(h2) : "f"(gf.y), "f"(gf.x));
    return h2;
}

DI void split2s(float v0, float v1, unsigned &hi, unsigned &lo){
    half h0 = __float2half_rn(v0), h1 = __float2half_rn(v1);
    half l0 = __float2half_rn(v0 - __half2float(h0));
    half l1 = __float2half_rn(v1 - __half2float(h1));
    hi = ((unsigned)__half_as_ushort(h1) << 16) | (unsigned)__half_as_ushort(h0);
    lo = ((unsigned)__half_as_ushort(l1) << 16) | (unsigned)__half_as_ushort(l0);
}

DI void mma16816(float (&c)[4], const unsigned (&a)[4], unsigned b0, unsigned b1){
    asm volatile(
        "mma.sync.aligned.m16n8k16.row.col.f32.f16.f16.f32 "
        "{%0,%1,%2,%3}, {%4,%5,%6,%7}, {%8,%9}, {%0,%1,%2,%3};"
        : "+f"(c[0]), "+f"(c[1]), "+f"(c[2]), "+f"(c[3])
        : "r"(a[0]), "r"(a[1]), "r"(a[2]), "r"(a[3]), "r"(b0), "r"(b1));
}

template<int NTI>
DI void init_acc1(float (&acc)[8][4], const float* bias, int lane){
    int t2 = (lane & 3) * 2;
    #pragma unroll
    for (int j = 0; j < NTI; j++){
        float2 b2v = *reinterpret_cast<const float2*>(bias + j*8 + t2);
        acc[j][0] = b2v.x; acc[j][1] = b2v.y;
        acc[j][2] = b2v.x; acc[j][3] = b2v.y;
    }
}

// one layer (single m-tile): Ah*Bh + Ah*Bl  (weights hi/lo packed in one uint4)
template<int KT, int NTI>
DI void mma_block1(float (&acc)[8][4],
                   const unsigned (&Ah)[4][4],
                   const uint4* __restrict__ wf, int lane){
    #pragma unroll
    for (int kt = 0; kt < KT; kt++){
        #pragma unroll
        for (int j = 0; j < NTI; j++){
            uint4 w = wf[(j*KT + kt)*32 + lane];
            mma16816(acc[j], Ah[kt], w.x, w.y);
            mma16816(acc[j], Ah[kt], w.z, w.w);
        }
    }
}

// D -> packed GELU -> next-layer A fragments (registers only)
DI void act_frags1(const float (&acc)[8][4], unsigned (&Ah)[4][4]){
    #pragma unroll
    for (int kk = 0; kk < 4; kk++)
    #pragma unroll
    for (int part = 0; part < 2; part++)
    #pragma unroll
    for (int pair = 0; pair < 2; pair++){
        int j = 2*kk + part;
        ull g = gelu2(pack2(acc[j][2*pair], acc[j][2*pair + 1]));
        Ah[kk][part*2 + pair] = cvt_h2(g);
    }
}

// A fragments for one 16-row m-tile from feature smem (row stride 40 halves)
template<int KT>
DI void load_feat_frags1(const half* __restrict__ fbase, int row0, int lane,
                         unsigned (&A)[4][4]){
    int g = lane >> 2, t2 = (lane & 3) * 2;
    int ra = row0 + g;
    #pragma unroll
    for (int kt = 0; kt < KT; kt++){
        const half* p0 = fbase + ra*40 + kt*16 + t2;
        const half* p1 = fbase + (ra + 8)*40 + kt*16 + t2;
        A[kt][0] = *reinterpret_cast<const unsigned*>(p0);
        A[kt][1] = *reinterpret_cast<const unsigned*>(p1);
        A[kt][2] = *reinterpret_cast<const unsigned*>(p0 + 8);
        A[kt][3] = *reinterpret_cast<const unsigned*>(p1 + 8);
    }
}

// stage weights into per-lane fragment order, fp16 hi/lo packed per uint4
DI void stage(char* sm, int off, const float* __restrict__ w,
              int Kreal, int Nreal, int ldw, int KT, int NTI, int tid){
    uint4* fq = reinterpret_cast<uint4*>(sm + off);
    int total = NTI * KT * 32;
    for (int idx = tid; idx < total; idx += NT){
        int lane = idx & 31;
        int kt   = (idx >> 5) % KT;
        int nt   = idx / (32 * KT);
        int n  = nt*8 + (lane >> 2);
        int k0 = kt*16 + (lane & 3)*2;
        float v[4];
        #pragma unroll
        for (int q = 0; q < 4; q++){
            int k = k0 + (q >> 1)*8 + (q & 1);
            v[q] = (k < Kreal && n < Nreal) ? w[k*ldw + n] : 0.0f;
        }
        unsigned hx, lx, hy, ly;
        split2s(v[0], v[1], hx, lx);
        split2s(v[2], v[3], hy, ly);
        fq[idx] = make_uint4(hx, hy, lx, ly);
    }
}

// layer-5 symmetrized weight: column n of w5s gives s-component n directly
DI float w5_sym(const float* __restrict__ w5, int k, int n){
    const float* r = w5 + k*9;
    switch(n){
        case 0: return r[0];
        case 1: return 0.5f*(r[1] + r[3]);
        case 2: return 0.5f*(r[2] + r[6]);
        case 3: return r[4];
        case 4: return 0.5f*(r[5] + r[7]);
        case 5: return r[8];
        default: return 0.0f;
    }
}

// ---------------- main fused kernel ----------------
__global__ void __launch_bounds__(NT, 3)
stress_hmma_kernel(const float* __restrict__ Fg, const float* __restrict__ Cg,
                   const float* __restrict__ w1, const float* __restrict__ b1,
                   const float* __restrict__ w2, const float* __restrict__ b2,
                   const float* __restrict__ w3, const float* __restrict__ b3,
                   const float* __restrict__ w4, const float* __restrict__ b4,
                   const float* __restrict__ w5, const float* __restrict__ b5,
                   const float* __restrict__ tlw, const int* __restrict__ traj_ids,
                   float* __restrict__ outg, int B)
{
    extern __shared__ __align__(16) char sm[];
    const int tid   = threadIdx.x;
    const int lane  = tid & 31;
    const int mrow0 = (tid >> 5) * 16;      // warp's m-tile base row (8 warps x 16 rows)
    const bool isPolar = (tid < TILE);      // warps 0-3: polar+epilogue; warps 4-7: features
    const int  item    = isPolar ? tid : (tid - TILE);

    // ---- stage weight fragments (once) ----
    stage(sm, O_WF1, w1, 25, 64, 64, 2, 8, tid);
    stage(sm, O_WF2, w2, 64, 64, 64, 4, 8, tid);
    stage(sm, O_WF3, w3, 64, 64, 64, 4, 8, tid);
    stage(sm, O_WF4, w4, 64, 64, 64, 4, 8, tid);
    // layer 5, symmetrized: N=8 (6 real), K=64 -> 4 kt x 1 ntile
    {
        uint4* fq = reinterpret_cast<uint4*>(sm + O_WF5);
        for (int idx = tid; idx < 128; idx += NT){
            int ln = idx & 31;
            int kt = idx >> 5;
            int n  = ln >> 2;
            int k0 = kt*16 + (ln & 3)*2;
            float v[4];
            #pragma unroll
            for (int q = 0; q < 4; q++){
                int k = k0 + (q >> 1)*8 + (q & 1);
                v[q] = w5_sym(w5, k, n);
            }
            unsigned hx, lx, hy, ly;
            split2s(v[0], v[1], hx, lx);
            split2s(v[2], v[3], hy, ly);
            fq[idx] = make_uint4(hx, hy, lx, ly);
        }
    }

    // ---- biases; fold constant latent into b1; symmetrize b5 ----
    float* sb = reinterpret_cast<float*>(sm + O_BIAS);
    if (tid < 64){
        int t = traj_ids[0];
        float a = b1[tid];
        #pragma unroll
        for (int e = 0; e < 32; e++)
            a = fmaf(tlw[t*32 + e], w1[(25+e)*64 + tid], a);
        sb[tid]       = a;
        sb[64  + tid] = b2[tid];
        sb[128 + tid] = b3[tid];
        sb[192 + tid] = b4[tid];
    }
    if (tid < 8){
        float bv = 0.0f;
        if (tid == 0) bv = b5[0];
        else if (tid == 1) bv = 0.5f*(b5[1] + b5[3]);
        else if (tid == 2) bv = 0.5f*(b5[2] + b5[6]);
        else if (tid == 3) bv = b5[4];
        else if (tid == 4) bv = 0.5f*(b5[5] + b5[7]);
        else if (tid == 5) bv = b5[8];
        sb[256 + tid] = bv;
    }
    __syncthreads();

    half*  fB   = reinterpret_cast<half*>(sm + O_FEAT);   // 128 rows x 40 halves
    float* outS = reinterpret_cast<float*>(sm + O_FEAT);  // alias: 128 rows x 20 floats
    int*   ctrS = reinterpret_cast<int*>(sm + O_CTR);     // dedicated slot (no alias)

    const uint4* WF1 = (const uint4*)(sm + O_WF1);
    const uint4* WF2 = (const uint4*)(sm + O_WF2);
    const uint4* WF3 = (const uint4*)(sm + O_WF3);
    const uint4* WF4 = (const uint4*)(sm + O_WF4);
    const uint4* WF5 = (const uint4*)(sm + O_WF5);

    const int tiles = (B + TILE - 1) / TILE;
    int myTile = blockIdx.x;

    while (myTile < tiles){
        const int  i  = myTile * TILE + item;
        const bool ok = (i < B);

        float f[9];
        float R0=1,R1=0,R2=0,R3=0,R4=1,R5=0,R6=0,R7=0,R8=1;

        // ---- load F (identity if OOB); both halves need it ----
        if (ok){
            #pragma unroll
            for (int a = 0; a < 9; a++) f[a] = Fg[(size_t)i*9 + a];
        } else {
            #pragma unroll
            for (int a = 0; a < 9; a++) f[a] = (a % 4 == 0) ? 1.0f : 0.0f;
        }

        if (isPolar){
            // ---- polar rotation: Newton X <- 0.5(X + X^-T), 5 iters ----
            R0=f[0];R1=f[1];R2=f[2];R3=f[3];R4=f[4];R5=f[5];R6=f[6];R7=f[7];R8=f[8];
            #pragma unroll 1
            for (int it = 0; it < 5; it++){
                float C00 = R4*R8 - R5*R7, C01 = R5*R6 - R3*R8, C02 = R3*R7 - R4*R6;
                float C10 = R2*R7 - R1*R8, C11 = R0*R8 - R2*R6, C12 = R1*R6 - R0*R7;
                float C20 = R1*R5 - R2*R4, C21 = R2*R3 - R0*R5, C22 = R0*R4 - R1*R3;
                float dR  = R0*C00 + R1*C01 + R2*C02;
                float hd  = 0.5f * rcp_a(dR);
                R0 = 0.5f*R0 + C00*hd; R1 = 0.5f*R1 + C01*hd; R2 = 0.5f*R2 + C02*hd;
                R3 = 0.5f*R3 + C10*hd; R4 = 0.5f*R4 + C11*hd; R5 = 0.5f*R5 + C12*hd;
                R6 = 0.5f*R6 + C20*hd; R7 = 0.5f*R7 + C21*hd; R8 = 0.5f*R8 + C22*hd;
            }
        } else {
            // ---- features for item = tid-128 ----
            float t00 = f[0]*f[0] + f[3]*f[3] + f[6]*f[6];
            float t01 = f[0]*f[1] + f[3]*f[4] + f[6]*f[7];
            float t02 = f[0]*f[2] + f[3]*f[5] + f[6]*f[8];
            float t11 = f[1]*f[1] + f[4]*f[4] + f[7]*f[7];
            float t12 = f[1]*f[2] + f[4]*f[5] + f[7]*f[8];
            float t22 = f[2]*f[2] + f[5]*f[5] + f[8]*f[8];

            float det = f[0]*(f[4]*f[8]-f[5]*f[7])
                      + f[1]*(f[5]*f[6]-f[3]*f[8])
                      + f[2]*(f[3]*f[7]-f[4]*f[6]);
            float dcl = (det < 0.0f) ? 1e-9f : det;

            float q  = (t00 + t11 + t22) * (1.0f/3.0f);
            float p1 = t01*t01 + t02*t02 + t12*t12;
            float m0 = t00 - q, m1 = t11 - q, m2 = t22 - q;
            float p2 = m0*m0 + m1*m1 + m2*m2 + 2.0f*p1;
            float p  = sqrt_a(p2 * (1.0f/6.0f) + 1e-30f);
            float ip = rcp_a(p);
            float b00 = m0*ip, b11 = m1*ip, b22 = m2*ip;
            float c01 = t01*ip, c02 = t02*ip, c12 = t12*ip;
            float detB = b00*(b11*b22 - c12*c12)
                       - c01*(c01*b22 - c12*c02)
                       + c02*(c01*c12 - b11*c02);
            float r = fminf(1.0f, fmaxf(-1.0f, 0.5f*detB));

            // acos via A&S 4.4.45 poly (|err| <= 6.7e-5 rad)
            float ar  = fabsf(r);
            float srt = sqrt_a(fmaxf(1.0f - ar, 0.0f));
            float pol = fmaf(fmaf(fmaf(-0.0187293f, ar, 0.0742610f), ar,
                                  -0.2121144f), ar, 1.5707288f);
            float ac  = srt * pol;
            float aco = (r >= 0.0f) ? ac : (3.14159265358979f - ac);
            float phi = aco * (1.0f/3.0f);

            float e1 = q + 2.0f*p*__cosf(phi);
            float e3 = q + 2.0f*p*__cosf(phi + 2.0943951023931953f);
            float e2 = 3.0f*q - e1 - e3;
            float s1 = sqrt_a(fmaxf(e1, 0.0f));
            float s2 = sqrt_a(fmaxf(e2, 0.0f));
            float s3 = sqrt_a(fmaxf(e3, 0.0f));

            float F00c = fmaxf(f[0], 1e-6f);

            float ft[32];
            ft[0]=s1; ft[1]=s2; ft[2]=s3;
            ft[3]=t00; ft[4]=t01; ft[5]=t02;
            ft[6]=t01; ft[7]=t11; ft[8]=t12;
            ft[9]=t02; ft[10]=t12; ft[11]=t22;
            ft[12]=dcl; ft[13]=__logf(dcl);
            ft[14]=F00c; ft[15]=__logf(F00c);
            #pragma unroll
            for (int a = 0; a < 9; a++)
                ft[16+a] = ok ? Cg[(size_t)i*9 + a] : 0.0f;
            #pragma unroll
            for (int a = 25; a < 32; a++) ft[a] = 0.0f;

            // vectorized feature store: 4 x STS.128
            uint4* wrow4 = reinterpret_cast<uint4*>(fB + item*40);
            #pragma unroll
            for (int c4 = 0; c4 < 4; c4++){
                __half2 h0 = __floats2half2_rn(ft[8*c4+0], ft[8*c4+1]);
                __half2 h1 = __floats2half2_rn(ft[8*c4+2], ft[8*c4+3]);
                __half2 h2 = __floats2half2_rn(ft[8*c4+4], ft[8*c4+5]);
                __half2 h3 = __floats2half2_rn(ft[8*c4+6], ft[8*c4+7]);
                wrow4[c4] = make_uint4(*reinterpret_cast<unsigned*>(&h0),
                                       *reinterpret_cast<unsigned*>(&h1),
                                       *reinterpret_cast<unsigned*>(&h2),
                                       *reinterpret_cast<unsigned*>(&h3));
            }
        }
        __syncthreads();                       // S1: features visible

        // grab next tile early; published at S3 (dedicated slot, no alias)
        if (tid == 0) *ctrS = atomicAdd(&g_tile_ctr, 1);

        float acc[8][4];
        unsigned Ah[4][4];

        load_feat_frags1<2>(fB, mrow0, lane, Ah);

        // ---- MLP on HMMA (2-product: Ah*Bh + Ah*Bl) ----
        init_acc1<8>(acc, sb, lane);
        mma_block1<2,8>(acc, Ah, WF1, lane);
        act_frags1(acc, Ah);

        init_acc1<8>(acc, sb + 64, lane);
        mma_block1<4,8>(acc, Ah, WF2, lane);
        act_frags1(acc, Ah);

        init_acc1<8>(acc, sb + 128, lane);
        mma_block1<4,8>(acc, Ah, WF3, lane);
        act_frags1(acc, Ah);

        init_acc1<8>(acc, sb + 192, lane);
        mma_block1<4,8>(acc, Ah, WF4, lane);
        act_frags1(acc, Ah);

        init_acc1<1>(acc, sb + 256, lane);
        mma_block1<4,1>(acc, Ah, WF5, lane);   // N=8: s-components directly

        // scatter targets only this warp's own 16 rows (same rows its frag loads
        // used), so a warp-level sync suffices here.
        __syncwarp();

        // ---- scatter layer-5 D (6 s-components, cols 0..5) to staging ----
        {
            int g = lane >> 2, t2 = (lane & 3) * 2;
            int row = mrow0 + g;
            *reinterpret_cast<float2*>(outS + row*20 + t2)     = make_float2(acc[0][0], acc[0][1]);
            *reinterpret_cast<float2*>(outS + (row+8)*20 + t2) = make_float2(acc[0][2], acc[0][3]);
        }
        __syncthreads();                       // S3: outS + next-tile slot visible

        int nextTile = *ctrS;

        if (isPolar && ok){
            const float* op = outS + item*20;
            float s00 = op[0], s01 = op[1], s02 = op[2];
            float s11 = op[3], s12 = op[4], s22 = op[5];

            float P00 = R0*s00 + R1*s01 + R2*s02;
            float P01 = R0*s01 + R1*s11 + R2*s12;
            float P02 = R0*s02 + R1*s12 + R2*s22;
            float P10 = R3*s00 + R4*s01 + R5*s02;
            float P11 = R3*s01 + R4*s11 + R5*s12;
            float P12 = R3*s02 + R4*s12 + R5*s22;
            float P20 = R6*s00 + R7*s01 + R8*s02;
            float P21 = R6*s01 + R7*s11 + R8*s12;
            float P22 = R6*s02 + R7*s12 + R8*s22;

            size_t o9 = (size_t)i*9;
            outg[o9+0] = P00*f[0] + P01*f[1] + P02*f[2];
            outg[o9+1] = P00*f[3] + P01*f[4] + P02*f[5];
            outg[o9+2] = P00*f[6] + P01*f[7] + P02*f[8];
            outg[o9+3] = P10*f[0] + P11*f[1] + P12*f[2];
            outg[o9+4] = P10*f[3] + P11*f[4] + P12*f[5];
            outg[o9+5] = P10*f[6] + P11*f[7] + P12*f[8];
            outg[o9+6] = P20*f[0] + P21*f[1] + P22*f[2];
            outg[o9+7] = P20*f[3] + P21*f[4] + P22*f[5];
            outg[o9+8] = P20*f[6] + P21*f[7] + P22*f[8];
        }

        __syncthreads();                       // S4: epilogue outS reads done before
                                               //     next iteration's feature writes
                                               //     (outS aliases fB)
        myTile = nextTile;
    }
}

// ---------------- launch ----------------
extern "C" void kernel_launch(void* const* d_in, const int* in_sizes, int n_in,
                              void* d_out, int out_size)
{
    const float* F   = (const float*)d_in[0];
    const float* C   = (const float*)d_in[1];
    const float* w1  = (const float*)d_in[2];
    const float* b1  = (const float*)d_in[3];
    const float* w2  = (const float*)d_in[4];
    const float* b2  = (const float*)d_in[5];
    const float* w3  = (const float*)d_in[6];
    const float* b3  = (const float*)d_in[7];
    const float* w4  = (const float*)d_in[8];
    const float* b4  = (const float*)d_in[9];
    const float* w5  = (const float*)d_in[10];
    const float* b5  = (const float*)d_in[11];
    const float* tlw = (const float*)d_in[12];
    const int*   tid = (const int*)d_in[13];
    float* out = (float*)d_out;

    int B = in_sizes[0] / 9;
    cudaFuncSetAttribute(stress_hmma_kernel,
                         cudaFuncAttributeMaxDynamicSharedMemorySize, SMEM_BYTES);

    int tiles = (B + TILE - 1) / TILE;
    int grid = tiles < 444 ? tiles : 444;   // 148 SMs x 3 CTAs

    reset_ctr_kernel<<<1, 1>>>(grid);       // counter starts past the static seeds
    stress_hmma_kernel<<<grid, NT, SMEM_BYTES>>>(
        F, C, w1, b1, w2, b2, w3, b3, w4, b4, w5, b5, tlw, tid, out, B);
}